// round 16
// baseline (speedup 1.0000x reference)
#include <cuda_runtime.h>
#include <math.h>

#define B_    8
#define T_    512
#define F_    229
#define C1_   48
#define C3_   96
#define FP1_  114
#define FP2_  57
#define DC_   768
#define FCIN_ 5472
#define G4_   3072
#define K1P_  1024   /* [emb 176 + pad 80 -> 256 | h1 768] */
#define K2_   1536
#define NP_   88
#define MALL_ 4096
#define NB_AR 128

// padded conv buffers
#define TP_   514
#define C1S_  232
#define C2S_  116

typedef unsigned long long u64t;

// ---------------- f32x2 helpers ----------------
__device__ __forceinline__ void fma2(u64t &acc, u64t a, u64t b) {
    asm("fma.rn.f32x2 %0, %1, %2, %0;" : "+l"(acc) : "l"(a), "l"(b));
}
__device__ __forceinline__ u64t pk2(float lo, float hi) {
    u64t r;
    asm("mov.b64 %0, {%1, %2};" : "=l"(r) : "r"(__float_as_uint(lo)), "r"(__float_as_uint(hi)));
    return r;
}
__device__ __forceinline__ float2 upk2(u64t v) {
    unsigned lo, hi;
    asm("mov.b64 {%0, %1}, %2;" : "=r"(lo), "=r"(hi) : "l"(v));
    return make_float2(__uint_as_float(lo), __uint_as_float(hi));
}
__device__ __forceinline__ float psum(u64t v) {
    float2 f = upk2(v);
    return f.x + f.y;
}
__device__ __forceinline__ u64t lo2(const float4& v) { return *reinterpret_cast<const u64t*>(&v.x); }
__device__ __forceinline__ u64t hi2(const float4& v) { return *reinterpret_cast<const u64t*>(&v.z); }

// ---------------- device scratch ----------------
__device__ float g_conv1p[B_*C1_*TP_*C1S_];
__device__ float g_conv2p[B_*C1_*TP_*C2S_];
__device__ float g_Amat[MALL_*FCIN_];
__device__ float g_ac[MALL_*DC_];
__device__ float g_pre[MALL_*G4_];
__device__ float g_W1r[G4_*K1P_];
__device__ float g_W2r[G4_*K2_];
__device__ float g_Wpre[G4_*DC_];
__device__ float g_bpre[G4_];
__device__ float g_b2v[G4_];
__device__ float g_wf1[C1_*9],      g_bf1[C1_];
__device__ float g_wf2[C1_*C1_*9],  g_bf2[C1_];
__device__ float g_wf3[C3_*C1_*9],  g_bf3[C3_];
__device__ float g_h1[2][B_][DC_], g_h2[2][B_][DC_];
__device__ float g_xemb[B_][176];
// barrier state: counter and release word on separate 128-B lines
__device__ unsigned g_cnt_pad[64];            /* [0] = arrival counter */
__device__ volatile unsigned g_rel_pad[64];   /* [0] = release word    */

// ---------------- prep ----------------
__global__ void prep_kernel(
    const float* __restrict__ c1w, const float* __restrict__ c1b,
    const float* __restrict__ b1g, const float* __restrict__ b1b,
    const float* __restrict__ b1m, const float* __restrict__ b1v,
    const float* __restrict__ c2w, const float* __restrict__ c2b,
    const float* __restrict__ b2g, const float* __restrict__ b2b,
    const float* __restrict__ b2m, const float* __restrict__ b2v,
    const float* __restrict__ c3w, const float* __restrict__ c3b,
    const float* __restrict__ b3g, const float* __restrict__ b3b,
    const float* __restrict__ b3m, const float* __restrict__ b3v,
    const float* __restrict__ wih1, const float* __restrict__ whh1,
    const float* __restrict__ bih1, const float* __restrict__ bhh1,
    const float* __restrict__ wih2, const float* __restrict__ whh2,
    const float* __restrict__ bih2, const float* __restrict__ bhh2,
    const float* __restrict__ embw)
{
    const int st = gridDim.x * blockDim.x;
    const int t0 = blockIdx.x * blockDim.x + threadIdx.x;
    const float eps = 1e-5f;

    // border-only zeroing of padded conv buffers
    {
        const int planes1 = B_*C1_;
        for (int i = t0; i < planes1 * C1S_; i += st) {
            int pl = i / C1S_, col = i - pl*C1S_;
            float* base = g_conv1p + (size_t)pl*TP_*C1S_;
            base[col] = 0.f;
            base[(size_t)(TP_-1)*C1S_ + col] = 0.f;
        }
        for (int i = t0; i < planes1 * 512; i += st) {
            int pl = i / 512, r = (i - pl*512) + 1;
            float* base = g_conv1p + (size_t)pl*TP_*C1S_ + (size_t)r*C1S_;
            base[0] = 0.f; base[230] = 0.f; base[231] = 0.f;
        }
        for (int i = t0; i < planes1 * C2S_; i += st) {
            int pl = i / C2S_, col = i - pl*C2S_;
            float* base = g_conv2p + (size_t)pl*TP_*C2S_;
            base[col] = 0.f;
            base[(size_t)(TP_-1)*C2S_ + col] = 0.f;
        }
        for (int i = t0; i < planes1 * 512; i += st) {
            int pl = i / 512, r = (i - pl*512) + 1;
            float* base = g_conv2p + (size_t)pl*TP_*C2S_ + (size_t)r*C2S_;
            base[0] = 0.f; base[115] = 0.f;
        }
    }

    for (int i = t0; i < C1_*9; i += st) { int c = i/9;        g_wf1[i] = c1w[i] * (b1g[c]*rsqrtf(b1v[c]+eps)); }
    for (int i = t0; i < C1_;  i += st)  g_bf1[i] = (c1b[i]-b1m[i])*(b1g[i]*rsqrtf(b1v[i]+eps)) + b1b[i];
    for (int i = t0; i < C1_*C1_*9; i += st) { int c = i/(C1_*9); g_wf2[i] = c2w[i] * (b2g[c]*rsqrtf(b2v[c]+eps)); }
    for (int i = t0; i < C1_;  i += st)  g_bf2[i] = (c2b[i]-b2m[i])*(b2g[i]*rsqrtf(b2v[i]+eps)) + b2b[i];
    for (int i = t0; i < C3_*C1_*9; i += st) { int c = i/(C1_*9); g_wf3[i] = c3w[i] * (b3g[c]*rsqrtf(b3v[c]+eps)); }
    for (int i = t0; i < C3_;  i += st)  g_bf3[i] = (c3b[i]-b3m[i])*(b3g[i]*rsqrtf(b3v[i]+eps)) + b3b[i];

    for (int i = t0; i < G4_*K1P_; i += st) {
        int n = i >> 10, k = i & (K1P_-1);
        int m = n >> 2, g = n & 3, orig = g*DC_ + m;
        float v = 0.f;
        if (k < 176)       v = wih1[orig*944 + 768 + k];
        else if (k >= 256) v = whh1[orig*DC_ + (k - 256)];
        g_W1r[i] = v;
    }
    for (int i = t0; i < G4_*K2_; i += st) {
        int n = i / K2_, k = i - n*K2_;
        int m = n >> 2, g = n & 3, orig = g*DC_ + m;
        g_W2r[i] = (k < DC_) ? wih2[orig*DC_ + k] : whh2[orig*DC_ + (k - DC_)];
    }
    for (int i = t0; i < G4_*DC_; i += st) {
        int n = i / DC_, k = i - n*DC_;
        int m = n >> 2, g = n & 3, orig = g*DC_ + m;
        g_Wpre[i] = wih1[orig*944 + k];
    }
    for (int i = t0; i < G4_; i += st) {
        int m = i >> 2, g = i & 3, orig = g*DC_ + m;
        g_bpre[i] = bih1[orig] + bhh1[orig];
        g_b2v[i]  = bih2[orig] + bhh2[orig];
    }
    for (int i = t0; i < B_*DC_; i += st) {
        (&g_h1[0][0][0])[i] = 0.f;
        (&g_h2[0][0][0])[i] = 0.f;
    }
    for (int i = t0; i < B_*176; i += st)
        (&g_xemb[0][0])[i] = embw[i & 1];
    if (t0 == 0) { g_cnt_pad[0] = 0u; g_rel_pad[0] = 0u; }
}

// ---------------- conv1: f32x2 over output-channel pairs ----------------
__global__ void conv1_kernel(const float* __restrict__ mel)
{
    int t = blockIdx.x, b = blockIdx.y, f = threadIdx.x;
    __shared__ u64t ws2[24*9];
    __shared__ u64t bs2[24];
    for (int i = threadIdx.x; i < 24*9; i += 256) {
        int cp = i / 9, r = i - cp*9;
        ws2[i] = pk2(g_wf1[(2*cp)*9 + r], g_wf1[(2*cp+1)*9 + r]);
    }
    for (int i = threadIdx.x; i < 24; i += 256)
        bs2[i] = pk2(g_bf1[2*i], g_bf1[2*i+1]);
    __syncthreads();
    if (f >= F_) return;

    float x[9];
#pragma unroll
    for (int dt = 0; dt < 3; dt++)
#pragma unroll
        for (int df = 0; df < 3; df++) {
            int tt = t - 1 + dt, ff = f - 1 + df;
            x[dt*3+df] = (tt >= 0 && tt < T_ && ff >= 0 && ff < F_)
                         ? mel[(b*T_ + tt)*F_ + ff] : 0.f;
        }
    u64t xk[9];
#pragma unroll
    for (int k = 0; k < 9; k++) xk[k] = pk2(x[k], x[k]);

    for (int cp = 0; cp < 24; cp++) {
        u64t a = bs2[cp];
#pragma unroll
        for (int k = 0; k < 9; k++) fma2(a, ws2[cp*9+k], xk[k]);
        float2 u = upk2(a);
        g_conv1p[((b*C1_ + 2*cp    )*TP_ + t + 1)*C1S_ + f + 1] = fmaxf(u.x, 0.f);
        g_conv1p[((b*C1_ + 2*cp + 1)*TP_ + t + 1)*C1S_ + f + 1] = fmaxf(u.y, 0.f);
    }
}

// ---------------- conv2: f32x2, shfl-based ReLU+maxpool epilogue ----------------
__global__ __launch_bounds__(256) void conv2_kernel()
{
    int t0 = blockIdx.x * 4, b = blockIdx.y, ch = blockIdx.z;
    int f = threadIdx.x;
    __shared__ u64t ws2[4*C1_*9];
    for (int i = threadIdx.x; i < 4*C1_*9; i += 256) {
        int p = i / (C1_*9), r = i - p*(C1_*9);
        ws2[i] = pk2(g_wf2[(ch*8 + 2*p)*C1_*9 + r],
                     g_wf2[(ch*8 + 2*p + 1)*C1_*9 + r]);
    }
    __syncthreads();

    u64t acc2[4][4];
#pragma unroll
    for (int p = 0; p < 4; p++) {
        u64t bp = pk2(g_bf2[ch*8 + 2*p], g_bf2[ch*8 + 2*p + 1]);
#pragma unroll
        for (int tt = 0; tt < 4; tt++) acc2[p][tt] = bp;
    }

    if (f < F_) {
        for (int ci = 0; ci < C1_; ci++) {
            const float* base = g_conv1p + ((b*C1_ + ci)*TP_ + t0)*C1S_ + f;
            float xr[6][3];
#pragma unroll
            for (int j = 0; j < 6; j++)
#pragma unroll
                for (int d = 0; d < 3; d++)
                    xr[j][d] = base[j*C1S_ + d];
#pragma unroll
            for (int k = 0; k < 9; k++) {
                const int dt = k / 3, df = k % 3;
                u64t xk0 = pk2(xr[dt  ][df], xr[dt  ][df]);
                u64t xk1 = pk2(xr[dt+1][df], xr[dt+1][df]);
                u64t xk2 = pk2(xr[dt+2][df], xr[dt+2][df]);
                u64t xk3 = pk2(xr[dt+3][df], xr[dt+3][df]);
#pragma unroll
                for (int p = 0; p < 4; p++) {
                    u64t wv = ws2[(p*C1_ + ci)*9 + k];
                    fma2(acc2[p][0], wv, xk0);
                    fma2(acc2[p][1], wv, xk1);
                    fma2(acc2[p][2], wv, xk2);
                    fma2(acc2[p][3], wv, xk3);
                }
            }
        }
    }
    float acc[8][4];
#pragma unroll
    for (int p = 0; p < 4; p++)
#pragma unroll
        for (int tt = 0; tt < 4; tt++) {
            float2 u = upk2(acc2[p][tt]);
            acc[2*p][tt] = u.x; acc[2*p+1][tt] = u.y;
        }

    // ReLU + maxpool via lane shuffle (pairs (2f',2f'+1) are adjacent lanes)
    const bool wr_ok = ((f & 1) == 0) && ((f >> 1) < FP1_);
#pragma unroll
    for (int cc = 0; cc < 8; cc++) {
        int c = ch*8 + cc;
#pragma unroll
        for (int tt = 0; tt < 4; tt++) {
            float v  = fmaxf(acc[cc][tt], 0.f);
            float vn = __shfl_down_sync(0xffffffffu, v, 1);
            if (wr_ok)
                g_conv2p[((b*C1_ + c)*TP_ + t0 + tt + 1)*C2S_ + (f >> 1) + 1] =
                    fmaxf(v, vn);
        }
    }
}

// ---------------- conv3: f32x2, shfl-based ReLU+maxpool epilogue ----------------
__global__ __launch_bounds__(128) void conv3_kernel()
{
    int t0 = blockIdx.x * 4, b = blockIdx.y, ch = blockIdx.z;
    int f = threadIdx.x;
    __shared__ u64t ws2[4*C1_*9];
    for (int i = threadIdx.x; i < 4*C1_*9; i += 128) {
        int p = i / (C1_*9), r = i - p*(C1_*9);
        ws2[i] = pk2(g_wf3[(ch*8 + 2*p)*C1_*9 + r],
                     g_wf3[(ch*8 + 2*p + 1)*C1_*9 + r]);
    }
    __syncthreads();

    u64t acc2[4][4];
#pragma unroll
    for (int p = 0; p < 4; p++) {
        u64t bp = pk2(g_bf3[ch*8 + 2*p], g_bf3[ch*8 + 2*p + 1]);
#pragma unroll
        for (int tt = 0; tt < 4; tt++) acc2[p][tt] = bp;
    }

    if (f < FP1_) {
        for (int ci = 0; ci < C1_; ci++) {
            const float* base = g_conv2p + ((b*C1_ + ci)*TP_ + t0)*C2S_ + f;
            float xr[6][3];
#pragma unroll
            for (int j = 0; j < 6; j++)
#pragma unroll
                for (int d = 0; d < 3; d++)
                    xr[j][d] = base[j*C2S_ + d];
#pragma unroll
            for (int k = 0; k < 9; k++) {
                const int dt = k / 3, df = k % 3;
                u64t xk0 = pk2(xr[dt  ][df], xr[dt  ][df]);
                u64t xk1 = pk2(xr[dt+1][df], xr[dt+1][df]);
                u64t xk2 = pk2(xr[dt+2][df], xr[dt+2][df]);
                u64t xk3 = pk2(xr[dt+3][df], xr[dt+3][df]);
#pragma unroll
                for (int p = 0; p < 4; p++) {
                    u64t wv = ws2[(p*C1_ + ci)*9 + k];
                    fma2(acc2[p][0], wv, xk0);
                    fma2(acc2[p][1], wv, xk1);
                    fma2(acc2[p][2], wv, xk2);
                    fma2(acc2[p][3], wv, xk3);
                }
            }
        }
    }
    float acc[8][4];
#pragma unroll
    for (int p = 0; p < 4; p++)
#pragma unroll
        for (int tt = 0; tt < 4; tt++) {
            float2 u = upk2(acc2[p][tt]);
            acc[2*p][tt] = u.x; acc[2*p+1][tt] = u.y;
        }

    const bool wr_ok = ((f & 1) == 0) && ((f >> 1) < FP2_);
#pragma unroll
    for (int cc = 0; cc < 8; cc++) {
        int c = ch*8 + cc;
#pragma unroll
        for (int tt = 0; tt < 4; tt++) {
            float v  = fmaxf(acc[cc][tt], 0.f);
            float vn = __shfl_down_sync(0xffffffffu, v, 1);
            if (wr_ok)
                g_Amat[(b*T_ + t0 + tt)*FCIN_ + c*FP2_ + (f >> 1)] =
                    fmaxf(v, vn);
        }
    }
}

// ---------------- GEMM ----------------
#define BM_ 128
#define BN_ 128
#define BK_ 16
#define ASTR 260
#define BSTR 132
#define GSMEM ((2*BK_*ASTR + 2*BK_*BSTR) * 4)

__global__ __launch_bounds__(256) void gemm_tn(
    const float* __restrict__ A, const float* __restrict__ Bm,
    const float* __restrict__ bias, float* __restrict__ C,
    int M, int N, int K)
{
    extern __shared__ float gsm[];
    float* As = gsm;
    float* Bs = gsm + 2*BK_*ASTR;

    const int tid = threadIdx.x;
    const int m0 = blockIdx.y * BM_, n0 = blockIdx.x * BN_;

    const int lr = tid >> 2;
    const int lk = (tid & 3) * 4;
    const float* Ap = A + (size_t)(m0 + lr) * K + lk;
    const float* Bp = Bm + (size_t)(n0 + lr) * K + lk;
    const size_t rowK = (size_t)64 * K;

    const int warp = tid >> 5, lane = tid & 31;
    const int wm = warp & 3, wn = warp >> 2;
    const int lm = lane >> 3, ln = lane & 7;
    const int row0 = wm * 32 + lm * 8;
    const int col0 = wn * 64 + ln * 8;

    u64t acc2[8][4];
#pragma unroll
    for (int i = 0; i < 8; i++)
#pragma unroll
        for (int j = 0; j < 4; j++) acc2[i][j] = 0ull;

    auto storeA = [&](int buf, const float4& a, int r) {
        float* p = As + (buf*BK_)*ASTR;
        *(float2*)&p[(lk+0)*ASTR + 2*r] = make_float2(a.x, a.x);
        *(float2*)&p[(lk+1)*ASTR + 2*r] = make_float2(a.y, a.y);
        *(float2*)&p[(lk+2)*ASTR + 2*r] = make_float2(a.z, a.z);
        *(float2*)&p[(lk+3)*ASTR + 2*r] = make_float2(a.w, a.w);
    };
    auto storeB = [&](int buf, const float4& b, int r) {
        float* p = Bs + (buf*BK_)*BSTR;
        p[(lk+0)*BSTR + r] = b.x;
        p[(lk+1)*BSTR + r] = b.y;
        p[(lk+2)*BSTR + r] = b.z;
        p[(lk+3)*BSTR + r] = b.w;
    };

    {
        float4 a0 = *(const float4*)(Ap);
        float4 a1 = *(const float4*)(Ap + rowK);
        float4 b0 = *(const float4*)(Bp);
        float4 b1 = *(const float4*)(Bp + rowK);
        storeA(0, a0, lr); storeA(0, a1, lr+64);
        storeB(0, b0, lr); storeB(0, b1, lr+64);
    }
    __syncthreads();

    const int nkt = K >> 4;
    int cur = 0;
    for (int kt = 0; kt < nkt; kt++) {
        float4 pa0, pa1, pb0, pb1;
        const bool has = (kt + 1 < nkt);
        if (has) {
            int ko = (kt + 1) << 4;
            pa0 = *(const float4*)(Ap + ko);
            pa1 = *(const float4*)(Ap + rowK + ko);
            pb0 = *(const float4*)(Bp + ko);
            pb1 = *(const float4*)(Bp + rowK + ko);
        }
#pragma unroll
        for (int kk = 0; kk < BK_; kk++) {
            const float* Ak = As + (cur*BK_ + kk)*ASTR + 2*row0;
            const float* Bk = Bs + (cur*BK_ + kk)*BSTR + col0;
            float4 ad0 = *(const float4*)(Ak);
            float4 ad1 = *(const float4*)(Ak + 4);
            float4 ad2 = *(const float4*)(Ak + 8);
            float4 ad3 = *(const float4*)(Ak + 12);
            float4 bv0 = *(const float4*)(Bk);
            float4 bv1 = *(const float4*)(Bk + 4);
            u64t ai[8] = {lo2(ad0), hi2(ad0), lo2(ad1), hi2(ad1),
                          lo2(ad2), hi2(ad2), lo2(ad3), hi2(ad3)};
            u64t bj[4] = {lo2(bv0), hi2(bv0), lo2(bv1), hi2(bv1)};
#pragma unroll
            for (int i = 0; i < 8; i++)
#pragma unroll
                for (int j = 0; j < 4; j++)
                    fma2(acc2[i][j], ai[i], bj[j]);
        }
        if (has) {
            int nb = cur ^ 1;
            storeA(nb, pa0, lr); storeA(nb, pa1, lr+64);
            storeB(nb, pb0, lr); storeB(nb, pb1, lr+64);
        }
        __syncthreads();
        cur ^= 1;
    }

    float bv[8];
#pragma unroll
    for (int j = 0; j < 8; j++) bv[j] = bias[n0 + col0 + j];
#pragma unroll
    for (int i = 0; i < 8; i++) {
        float* Cp = C + (size_t)(m0 + row0 + i) * N + n0 + col0;
        float2 r0 = upk2(acc2[i][0]), r1 = upk2(acc2[i][1]);
        float2 r2 = upk2(acc2[i][2]), r3 = upk2(acc2[i][3]);
        float4 o0 = make_float4(r0.x+bv[0], r0.y+bv[1], r1.x+bv[2], r1.y+bv[3]);
        float4 o1 = make_float4(r2.x+bv[4], r2.y+bv[5], r3.x+bv[6], r3.y+bv[7]);
        *(float4*)(Cp)     = o0;
        *(float4*)(Cp + 4) = o1;
    }
}

// ---------------- AR persistent kernel ----------------
__device__ __forceinline__ float warp_sum(float s)
{
    s += __shfl_xor_sync(0xffffffffu, s, 16);
    s += __shfl_xor_sync(0xffffffffu, s, 8);
    s += __shfl_xor_sync(0xffffffffu, s, 4);
    s += __shfl_xor_sync(0xffffffffu, s, 2);
    s += __shfl_xor_sync(0xffffffffu, s, 1);
    return s;
}
__device__ __forceinline__ float sigm(float x) { return 1.f / (1.f + expf(-x)); }

// arrival counter + release word, on separate cache lines
__device__ __forceinline__ void gbar(unsigned gen)
{
    __syncthreads();
    if (threadIdx.x == 0) {
        __threadfence();
        unsigned a = atomicAdd(&g_cnt_pad[0], 1u) + 1u;
        if (a == gen * NB_AR) {
            g_rel_pad[0] = gen;
        } else {
            while (g_rel_pad[0] < gen) { }
        }
    }
    __syncthreads();
}

// staged pairwise reduction
__device__ __forceinline__ void reduce32(float* v, int lane)
{
#pragma unroll
    for (int o = 16; o > 0; o >>= 1) {
        bool hi = (lane & o) != 0;
#pragma unroll
        for (int i = 0; i < o; i++) {
            float a0 = v[i], a1 = v[i + o];
            float mine = hi ? a1 : a0;
            float send = hi ? a0 : a1;
            float other = __shfl_xor_sync(0xffffffffu, send, o);
            v[i] = mine + other;
        }
    }
}

template<int NITER>
__device__ __forceinline__ void gemv_part(
    const float* __restrict__ Wb, int wstride,
    const float* xb, int xstride, int lane, float* v)
{
    u64t acc[4][8];
#pragma unroll
    for (int r = 0; r < 4; r++)
#pragma unroll
        for (int b = 0; b < 8; b++) acc[r][b] = 0ull;

#pragma unroll
    for (int it = 0; it < NITER; it++) {
        int off = it * 128 + lane * 4;
        float4 w0 = *(const float4*)(Wb              + off);
        float4 w1 = *(const float4*)(Wb +   wstride  + off);
        float4 w2 = *(const float4*)(Wb + 2*wstride  + off);
        float4 w3 = *(const float4*)(Wb + 3*wstride  + off);
#pragma unroll
        for (int b = 0; b < 8; b++) {
            float4 x = *(const float4*)(xb + b*xstride + off);
            u64t x0 = lo2(x), x1 = hi2(x);
            fma2(acc[0][b], lo2(w0), x0); fma2(acc[0][b], hi2(w0), x1);
            fma2(acc[1][b], lo2(w1), x0); fma2(acc[1][b], hi2(w1), x1);
            fma2(acc[2][b], lo2(w2), x0); fma2(acc[2][b], hi2(w2), x1);
            fma2(acc[3][b], lo2(w3), x0); fma2(acc[3][b], hi2(w3), x1);
        }
    }
#pragma unroll
    for (int r = 0; r < 4; r++)
#pragma unroll
        for (int b = 0; b < 8; b++) v[r*8 + b] = psum(acc[r][b]);
}

// smem float offsets (58096 floats = 232384 B <= 232448 B limit)
#define SW2   0        /* 6*4*1536 = 36864 */
#define SWP   36864    /* 2*5*768  =  7680 */
#define SXS   44544    /* 8*1536   = 12288 */
#define SP2   56832    /* 384 */
#define SPH   57216    /* 384 */
#define SPRE  57600    /* 384 */
#define SC1   57984    /* 48 */
#define SC2   58032    /* 48 */
#define SEMB  58080    /* 16 (10 used) */
#define STOT  58096

__global__ __launch_bounds__(384, 1) void ar_kernel(
    const float* __restrict__ postw, const float* __restrict__ postb,
    const float* __restrict__ embw, float* __restrict__ out)
{
    extern __shared__ float sm[];
    float* w2s  = sm + SW2;
    float* wps  = sm + SWP;
    float* xs2  = sm + SXS;
    float* p2   = sm + SP2;
    float* ph   = sm + SPH;
    float* preS = sm + SPRE;
    float* c1s  = sm + SC1;
    float* c2s  = sm + SC2;
    float* embS = sm + SEMB;

    const int tid = threadIdx.x, lane = tid & 31, warp = tid >> 5;
    const int cl = warp >> 1, half = warp & 1;
    const int cell = blockIdx.x * 6 + cl;

    // ---- one-time loads ----
    {
        const float4* src = (const float4*)(g_W2r + (size_t)blockIdx.x * 6 * 4 * K2_);
        float4* dst = (float4*)w2s;
        for (int i = tid; i < 6*4*K2_/4; i += 384) dst[i] = src[i];
    }
    {
        const float4* s0 = (const float4*)(postw + (size_t)(blockIdx.x >> 1) * 5 * DC_);
        float4* d0 = (float4*)wps;
        for (int i = tid; i < 5*DC_/4; i += 384) d0[i] = s0[i];
        if (blockIdx.x < 48) {
            const float4* s1 = (const float4*)(postw + (size_t)((NB_AR + blockIdx.x) >> 1) * 5 * DC_);
            float4* d1 = (float4*)(wps + 5*DC_);
            for (int i = tid; i < 5*DC_/4; i += 384) d1[i] = s1[i];
        }
    }
    for (int i = tid; i < 12288; i += 384) xs2[i] = 0.f;
    for (int i = tid; i < 384;   i += 384) ph[i] = 0.f;
    if (tid < 48) { c1s[tid] = 0.f; c2s[tid] = 0.f; }
    if (tid < 10) embS[tid] = embw[tid];
    if (tid < 192) {
        int b = tid / 24, j = tid - b*24;
        preS[tid] = __ldg(&g_pre[(size_t)(b*T_)*G4_ + blockIdx.x*24 + j]);
    }
    __syncthreads();

    float v[32];
    unsigned gen = 0;

    for (int t = 0; t < T_; t++) {
        const int wr = (t & 1) ^ 1, pbuf = t & 1;

        // ======== Phase A: emb-part GEMV + combine -> h1_new ========
        for (int i = tid; i < B_*44; i += 384) {
            int b = i / 44, j = i - b*44;
            ((float4*)(xs2 + b*K2_))[j] = __ldcg((const float4*)&g_xemb[b][0] + j);
        }
        __syncthreads();
        gemv_part<1>(g_W1r + (size_t)cell*4*K1P_ + half*128, K1P_,
                     xs2 + half*128, K2_, lane, v);
        reduce32(v, lane);
        p2[warp*32 + lane] = v[0];
        __syncthreads();
        if (tid < 48) {
            int c = tid >> 3, b = tid & 7;
            int mycell = blockIdx.x*6 + c;
            float z[4];
#pragma unroll
            for (int r = 0; r < 4; r++) {
                int idx = r*8 + b;
                z[r] = p2[(c*2)*32 + idx] + p2[(c*2+1)*32 + idx]
                     + ph[(c*2)*32 + idx] + ph[(c*2+1)*32 + idx]
                     + preS[pbuf*192 + b*24 + c*4 + r];
            }
            float co = c1s[tid];
            float ig = sigm(z[0]), fg = sigm(z[1]);
            float gg = tanhf(z[2]), og = sigm(z[3]);
            float cn = fg*co + ig*gg;
            c1s[tid] = cn;
            g_h1[wr][b][mycell] = og * tanhf(cn);
        }
        gbar(++gen);

        // ======== Phase B: LSTM2 ========
        for (int i = tid; i < B_*(DC_/4); i += 384) {
            int b = i / (DC_/4), j = i - b*(DC_/4);
            ((float4*)(xs2 + b*K2_))[j] = __ldcg((const float4*)&g_h1[wr][b][0] + j);
        }
        __syncthreads();
        gemv_part<6>(w2s + cl*4*K2_ + half*DC_, K2_,
                     xs2 + half*DC_, K2_, lane, v);
        reduce32(v, lane);
        p2[warp*32 + lane] = v[0];
        __syncthreads();
        if (tid < 48) {
            int c = tid >> 3, b = tid & 7;
            int mycell = blockIdx.x*6 + c;
            float z[4];
#pragma unroll
            for (int r = 0; r < 4; r++) {
                int idx = r*8 + b;
                z[r] = p2[(c*2)*32 + idx] + p2[(c*2+1)*32 + idx]
                     + __ldg(&g_b2v[mycell*4 + r]);
            }
            float co = c2s[tid];
            float ig = sigm(z[0]), fg = sigm(z[1]);
            float gg = tanhf(z[2]), og = sigm(z[3]);
            float cn = fg*co + ig*gg;
            c2s[tid] = cn;
            g_h2[wr][b][mycell] = og * tanhf(cn);
        }
        gbar(++gen);

        // ======== Phase C: stage h2_new; deferred h1 GEMV; post + argmax ========
        for (int i = tid; i < B_*(DC_/4); i += 384) {
            int b = i / (DC_/4), j = i - b*(DC_/4);
            ((float4*)(xs2 + b*K2_ + DC_))[j] = __ldcg((const float4*)&g_h2[wr][b][0] + j);
        }
        if (t + 1 < T_ && tid < 192) {
            int b = tid / 24, j = tid - b*24;
            preS[(pbuf^1)*192 + tid] = __ldg(&g_pre[(size_t)(b*T_ + t + 1)*G4_ + blockIdx.x*24 + j]);
        }
        __syncthreads();

        gemv_part<3>(g_W1r + (size_t)cell*4*K1P_ + 256 + half*384, K1P_,
                     xs2 + half*384, K2_, lane, v);
        reduce32(v, lane);
        ph[warp*32 + lane] = v[0];

        if (warp < 2 && (warp == 0 || blockIdx.x < 48)) {
            int task = warp * NB_AR + blockIdx.x;
            int p = task >> 1, bh = (task & 1) * 4;
            const float* Wp = wps + warp * 5 * DC_;
            u64t acc[5][4];
#pragma unroll
            for (int s = 0; s < 5; s++)
#pragma unroll
                for (int b = 0; b < 4; b++) acc[s][b] = 0ull;
#pragma unroll 2
            for (int kb = 0; kb < DC_; kb += 128) {
                int off = kb + lane*4;
                float4 w[5];
#pragma unroll
                for (int s = 0; s < 5; s++)
                    w[s] = *(const float4*)(Wp + s*DC_ + off);
#pragma unroll
                for (int b = 0; b < 4; b++) {
                    float4 x = *(const float4*)(xs2 + (bh + b)*K2_ + DC_ + off);
                    u64t x0 = lo2(x), x1 = hi2(x);
#pragma unroll
                    for (int s = 0; s < 5; s++) {
                        fma2(acc[s][b], lo2(w[s]), x0);
                        fma2(acc[s][b], hi2(w[s]), x1);
                    }
                }
            }
            float z[5][4];
#pragma unroll
            for (int s = 0; s < 5; s++)
#pragma unroll
                for (int b = 0; b < 4; b++)
                    z[s][b] = warp_sum(psum(acc[s][b]));
            if (lane < 4) {
                int b = bh + lane;
                float* o = out + (size_t)(b*T_ + t)*440 + p*5;
                float best = -1e30f; int bi = 0;
#pragma unroll
                for (int s = 0; s < 5; s++) {
                    float v0 = (lane & 1) ? z[s][1] : z[s][0];
                    float v1 = (lane & 1) ? z[s][3] : z[s][2];
                    float vv = ((lane & 2) ? v1 : v0) + __ldg(&postb[p*5 + s]);
                    o[s] = vv;
                    if (vv > best) { best = vv; bi = s; }
                }
                g_xemb[b][p*2]     = embS[bi*2];
                g_xemb[b][p*2 + 1] = embS[bi*2 + 1];
            }
        }
        gbar(++gen);
    }
}

// ---------------- launch ----------------
extern "C" void kernel_launch(void* const* d_in, const int* in_sizes, int n_in,
                              void* d_out, int out_size)
{
    const float* mel    = (const float*)d_in[0];
    const float* c1w    = (const float*)d_in[1];
    const float* c1b    = (const float*)d_in[2];
    const float* b1g    = (const float*)d_in[3];
    const float* b1b    = (const float*)d_in[4];
    const float* b1m    = (const float*)d_in[5];
    const float* b1v    = (const float*)d_in[6];
    const float* c2w    = (const float*)d_in[7];
    const float* c2b    = (const float*)d_in[8];
    const float* b2g    = (const float*)d_in[9];
    const float* b2b    = (const float*)d_in[10];
    const float* b2m    = (const float*)d_in[11];
    const float* b2v    = (const float*)d_in[12];
    const float* c3w    = (const float*)d_in[13];
    const float* c3b    = (const float*)d_in[14];
    const float* b3g    = (const float*)d_in[15];
    const float* b3b    = (const float*)d_in[16];
    const float* b3m    = (const float*)d_in[17];
    const float* b3v    = (const float*)d_in[18];
    const float* fc_w   = (const float*)d_in[19];
    const float* fc_b   = (const float*)d_in[20];
    const float* wih1   = (const float*)d_in[21];
    const float* whh1   = (const float*)d_in[22];
    const float* bih1   = (const float*)d_in[23];
    const float* bhh1   = (const float*)d_in[24];
    const float* wih2   = (const float*)d_in[25];
    const float* whh2   = (const float*)d_in[26];
    const float* bih2   = (const float*)d_in[27];
    const float* bhh2   = (const float*)d_in[28];
    const float* post_w = (const float*)d_in[29];
    const float* post_b = (const float*)d_in[30];
    const float* emb_w  = (const float*)d_in[31];

    prep_kernel<<<2048, 256>>>(c1w, c1b, b1g, b1b, b1m, b1v,
                               c2w, c2b, b2g, b2b, b2m, b2v,
                               c3w, c3b, b3g, b3b, b3m, b3v,
                               wih1, whh1, bih1, bhh1,
                               wih2, whh2, bih2, bhh2, emb_w);

    conv1_kernel<<<dim3(T_, B_), 256>>>(mel);
    conv2_kernel<<<dim3(T_/4, B_, C1_/8), 256>>>();
    conv3_kernel<<<dim3(T_/4, B_, C3_/8), 128>>>();

    float *pA, *pAc, *pPre, *pWpre, *pBpre;
    cudaGetSymbolAddress((void**)&pA,    g_Amat);
    cudaGetSymbolAddress((void**)&pAc,   g_ac);
    cudaGetSymbolAddress((void**)&pPre,  g_pre);
    cudaGetSymbolAddress((void**)&pWpre, g_Wpre);
    cudaGetSymbolAddress((void**)&pBpre, g_bpre);

    cudaFuncSetAttribute(gemm_tn, cudaFuncAttributeMaxDynamicSharedMemorySize, GSMEM);
    gemm_tn<<<dim3(DC_/BN_, MALL_/BM_), 256, GSMEM>>>(pA, fc_w, fc_b, pAc, MALL_, DC_, FCIN_);
    gemm_tn<<<dim3(G4_/BN_, MALL_/BM_), 256, GSMEM>>>(pAc, pWpre, pBpre, pPre, MALL_, G4_, DC_);

    const int ar_smem = STOT * (int)sizeof(float);  // 232384 B
    cudaFuncSetAttribute(ar_kernel, cudaFuncAttributeMaxDynamicSharedMemorySize, ar_smem);
    ar_kernel<<<NB_AR, 384, ar_smem>>>(post_w, post_b, emb_w, (float*)d_out);
}

// round 17
// speedup vs baseline: 1.5030x; 1.5030x over previous
#include <cuda_runtime.h>
#include <math.h>

#define B_    8
#define T_    512
#define F_    229
#define C1_   48
#define C3_   96
#define FP1_  114
#define FP2_  57
#define DC_   768
#define FCIN_ 5472
#define G4_   3072
#define K1P_  1024   /* [emb 176 + pad 80 -> 256 | h1 768] */
#define K2_   1536
#define NP_   88
#define MALL_ 4096
#define NB_AR 128

// padded conv buffers
#define TP_   514
#define C1S_  232
#define C2S_  116

typedef unsigned long long u64t;

// ---------------- f32x2 helpers ----------------
__device__ __forceinline__ void fma2(u64t &acc, u64t a, u64t b) {
    asm("fma.rn.f32x2 %0, %1, %2, %0;" : "+l"(acc) : "l"(a), "l"(b));
}
__device__ __forceinline__ u64t pk2(float lo, float hi) {
    u64t r;
    asm("mov.b64 %0, {%1, %2};" : "=l"(r) : "r"(__float_as_uint(lo)), "r"(__float_as_uint(hi)));
    return r;
}
__device__ __forceinline__ float2 upk2(u64t v) {
    unsigned lo, hi;
    asm("mov.b64 {%0, %1}, %2;" : "=r"(lo), "=r"(hi) : "l"(v));
    return make_float2(__uint_as_float(lo), __uint_as_float(hi));
}
__device__ __forceinline__ float psum(u64t v) {
    float2 f = upk2(v);
    return f.x + f.y;
}
__device__ __forceinline__ u64t lo2(const float4& v) { return *reinterpret_cast<const u64t*>(&v.x); }
__device__ __forceinline__ u64t hi2(const float4& v) { return *reinterpret_cast<const u64t*>(&v.z); }

// ---------------- device scratch ----------------
__device__ float g_conv1p[B_*C1_*TP_*C1S_];
__device__ float g_conv2p[B_*C1_*TP_*C2S_];
__device__ float g_Amat[MALL_*FCIN_];
__device__ float g_ac[MALL_*DC_];
__device__ float g_pre[MALL_*G4_];
__device__ float g_W1r[G4_*K1P_];
__device__ float g_W2r[G4_*K2_];
__device__ float g_Wpre[G4_*DC_];
__device__ float g_bpre[G4_];
__device__ float g_b2v[G4_];
__device__ float g_wf1[C1_*9],      g_bf1[C1_];
__device__ float g_wf2[C1_*C1_*9],  g_bf2[C1_];
__device__ float g_wf3[C3_*C1_*9],  g_bf3[C3_];
__device__ float g_h1[2][B_][DC_], g_h2[2][B_][DC_];
__device__ float g_xemb[B_][176];
__device__ unsigned g_cnt2;
__device__ volatile unsigned g_rel2;

// ---------------- prep ----------------
__global__ void prep_kernel(
    const float* __restrict__ c1w, const float* __restrict__ c1b,
    const float* __restrict__ b1g, const float* __restrict__ b1b,
    const float* __restrict__ b1m, const float* __restrict__ b1v,
    const float* __restrict__ c2w, const float* __restrict__ c2b,
    const float* __restrict__ b2g, const float* __restrict__ b2b,
    const float* __restrict__ b2m, const float* __restrict__ b2v,
    const float* __restrict__ c3w, const float* __restrict__ c3b,
    const float* __restrict__ b3g, const float* __restrict__ b3b,
    const float* __restrict__ b3m, const float* __restrict__ b3v,
    const float* __restrict__ wih1, const float* __restrict__ whh1,
    const float* __restrict__ bih1, const float* __restrict__ bhh1,
    const float* __restrict__ wih2, const float* __restrict__ whh2,
    const float* __restrict__ bih2, const float* __restrict__ bhh2,
    const float* __restrict__ embw)
{
    const int st = gridDim.x * blockDim.x;
    const int t0 = blockIdx.x * blockDim.x + threadIdx.x;
    const float eps = 1e-5f;

    // border-only zeroing of padded conv buffers
    {
        const int planes1 = B_*C1_;
        for (int i = t0; i < planes1 * C1S_; i += st) {
            int pl = i / C1S_, col = i - pl*C1S_;
            float* base = g_conv1p + (size_t)pl*TP_*C1S_;
            base[col] = 0.f;
            base[(size_t)(TP_-1)*C1S_ + col] = 0.f;
        }
        for (int i = t0; i < planes1 * 512; i += st) {
            int pl = i / 512, r = (i - pl*512) + 1;
            float* base = g_conv1p + (size_t)pl*TP_*C1S_ + (size_t)r*C1S_;
            base[0] = 0.f; base[230] = 0.f; base[231] = 0.f;
        }
        for (int i = t0; i < planes1 * C2S_; i += st) {
            int pl = i / C2S_, col = i - pl*C2S_;
            float* base = g_conv2p + (size_t)pl*TP_*C2S_;
            base[col] = 0.f;
            base[(size_t)(TP_-1)*C2S_ + col] = 0.f;
        }
        for (int i = t0; i < planes1 * 512; i += st) {
            int pl = i / 512, r = (i - pl*512) + 1;
            float* base = g_conv2p + (size_t)pl*TP_*C2S_ + (size_t)r*C2S_;
            base[0] = 0.f; base[115] = 0.f;
        }
    }

    for (int i = t0; i < C1_*9; i += st) { int c = i/9;        g_wf1[i] = c1w[i] * (b1g[c]*rsqrtf(b1v[c]+eps)); }
    for (int i = t0; i < C1_;  i += st)  g_bf1[i] = (c1b[i]-b1m[i])*(b1g[i]*rsqrtf(b1v[i]+eps)) + b1b[i];
    for (int i = t0; i < C1_*C1_*9; i += st) { int c = i/(C1_*9); g_wf2[i] = c2w[i] * (b2g[c]*rsqrtf(b2v[c]+eps)); }
    for (int i = t0; i < C1_;  i += st)  g_bf2[i] = (c2b[i]-b2m[i])*(b2g[i]*rsqrtf(b2v[i]+eps)) + b2b[i];
    for (int i = t0; i < C3_*C1_*9; i += st) { int c = i/(C1_*9); g_wf3[i] = c3w[i] * (b3g[c]*rsqrtf(b3v[c]+eps)); }
    for (int i = t0; i < C3_;  i += st)  g_bf3[i] = (c3b[i]-b3m[i])*(b3g[i]*rsqrtf(b3v[i]+eps)) + b3b[i];

    for (int i = t0; i < G4_*K1P_; i += st) {
        int n = i >> 10, k = i & (K1P_-1);
        int m = n >> 2, g = n & 3, orig = g*DC_ + m;
        float v = 0.f;
        if (k < 176)       v = wih1[orig*944 + 768 + k];
        else if (k >= 256) v = whh1[orig*DC_ + (k - 256)];
        g_W1r[i] = v;
    }
    for (int i = t0; i < G4_*K2_; i += st) {
        int n = i / K2_, k = i - n*K2_;
        int m = n >> 2, g = n & 3, orig = g*DC_ + m;
        g_W2r[i] = (k < DC_) ? wih2[orig*DC_ + k] : whh2[orig*DC_ + (k - DC_)];
    }
    for (int i = t0; i < G4_*DC_; i += st) {
        int n = i / DC_, k = i - n*DC_;
        int m = n >> 2, g = n & 3, orig = g*DC_ + m;
        g_Wpre[i] = wih1[orig*944 + k];
    }
    for (int i = t0; i < G4_; i += st) {
        int m = i >> 2, g = i & 3, orig = g*DC_ + m;
        g_bpre[i] = bih1[orig] + bhh1[orig];
        g_b2v[i]  = bih2[orig] + bhh2[orig];
    }
    for (int i = t0; i < B_*DC_; i += st) {
        (&g_h1[0][0][0])[i] = 0.f;
        (&g_h2[0][0][0])[i] = 0.f;
    }
    for (int i = t0; i < B_*176; i += st)
        (&g_xemb[0][0])[i] = embw[i & 1];
    if (t0 == 0) { g_cnt2 = 0u; g_rel2 = 0u; }
}

// ---------------- conv1: f32x2 over output-channel pairs ----------------
__global__ void conv1_kernel(const float* __restrict__ mel)
{
    int t = blockIdx.x, b = blockIdx.y, f = threadIdx.x;
    __shared__ u64t ws2[24*9];
    __shared__ u64t bs2[24];
    for (int i = threadIdx.x; i < 24*9; i += 256) {
        int cp = i / 9, r = i - cp*9;
        ws2[i] = pk2(g_wf1[(2*cp)*9 + r], g_wf1[(2*cp+1)*9 + r]);
    }
    for (int i = threadIdx.x; i < 24; i += 256)
        bs2[i] = pk2(g_bf1[2*i], g_bf1[2*i+1]);
    __syncthreads();
    if (f >= F_) return;

    float x[9];
#pragma unroll
    for (int dt = 0; dt < 3; dt++)
#pragma unroll
        for (int df = 0; df < 3; df++) {
            int tt = t - 1 + dt, ff = f - 1 + df;
            x[dt*3+df] = (tt >= 0 && tt < T_ && ff >= 0 && ff < F_)
                         ? mel[(b*T_ + tt)*F_ + ff] : 0.f;
        }
    u64t xk[9];
#pragma unroll
    for (int k = 0; k < 9; k++) xk[k] = pk2(x[k], x[k]);

    for (int cp = 0; cp < 24; cp++) {
        u64t a = bs2[cp];
#pragma unroll
        for (int k = 0; k < 9; k++) fma2(a, ws2[cp*9+k], xk[k]);
        float2 u = upk2(a);
        g_conv1p[((b*C1_ + 2*cp    )*TP_ + t + 1)*C1S_ + f + 1] = fmaxf(u.x, 0.f);
        g_conv1p[((b*C1_ + 2*cp + 1)*TP_ + t + 1)*C1S_ + f + 1] = fmaxf(u.y, 0.f);
    }
}

// ---------------- conv2: f32x2, shfl-based ReLU+maxpool epilogue ----------------
__global__ __launch_bounds__(256) void conv2_kernel()
{
    int t0 = blockIdx.x * 4, b = blockIdx.y, ch = blockIdx.z;
    int f = threadIdx.x;
    __shared__ u64t ws2[4*C1_*9];
    for (int i = threadIdx.x; i < 4*C1_*9; i += 256) {
        int p = i / (C1_*9), r = i - p*(C1_*9);
        ws2[i] = pk2(g_wf2[(ch*8 + 2*p)*C1_*9 + r],
                     g_wf2[(ch*8 + 2*p + 1)*C1_*9 + r]);
    }
    __syncthreads();

    u64t acc2[4][4];
#pragma unroll
    for (int p = 0; p < 4; p++) {
        u64t bp = pk2(g_bf2[ch*8 + 2*p], g_bf2[ch*8 + 2*p + 1]);
#pragma unroll
        for (int tt = 0; tt < 4; tt++) acc2[p][tt] = bp;
    }

    if (f < F_) {
        for (int ci = 0; ci < C1_; ci++) {
            const float* base = g_conv1p + ((b*C1_ + ci)*TP_ + t0)*C1S_ + f;
            float xr[6][3];
#pragma unroll
            for (int j = 0; j < 6; j++)
#pragma unroll
                for (int d = 0; d < 3; d++)
                    xr[j][d] = base[j*C1S_ + d];
#pragma unroll
            for (int k = 0; k < 9; k++) {
                const int dt = k / 3, df = k % 3;
                u64t xk0 = pk2(xr[dt  ][df], xr[dt  ][df]);
                u64t xk1 = pk2(xr[dt+1][df], xr[dt+1][df]);
                u64t xk2 = pk2(xr[dt+2][df], xr[dt+2][df]);
                u64t xk3 = pk2(xr[dt+3][df], xr[dt+3][df]);
#pragma unroll
                for (int p = 0; p < 4; p++) {
                    u64t wv = ws2[(p*C1_ + ci)*9 + k];
                    fma2(acc2[p][0], wv, xk0);
                    fma2(acc2[p][1], wv, xk1);
                    fma2(acc2[p][2], wv, xk2);
                    fma2(acc2[p][3], wv, xk3);
                }
            }
        }
    }
    float acc[8][4];
#pragma unroll
    for (int p = 0; p < 4; p++)
#pragma unroll
        for (int tt = 0; tt < 4; tt++) {
            float2 u = upk2(acc2[p][tt]);
            acc[2*p][tt] = u.x; acc[2*p+1][tt] = u.y;
        }

    // ReLU + maxpool via lane shuffle (pool pairs are adjacent lanes)
    const bool wr_ok = ((f & 1) == 0) && ((f >> 1) < FP1_);
#pragma unroll
    for (int cc = 0; cc < 8; cc++) {
        int c = ch*8 + cc;
#pragma unroll
        for (int tt = 0; tt < 4; tt++) {
            float v  = fmaxf(acc[cc][tt], 0.f);
            float vn = __shfl_down_sync(0xffffffffu, v, 1);
            if (wr_ok)
                g_conv2p[((b*C1_ + c)*TP_ + t0 + tt + 1)*C2S_ + (f >> 1) + 1] =
                    fmaxf(v, vn);
        }
    }
}

// ---------------- conv3: f32x2, shfl-based ReLU+maxpool epilogue ----------------
__global__ __launch_bounds__(128) void conv3_kernel()
{
    int t0 = blockIdx.x * 4, b = blockIdx.y, ch = blockIdx.z;
    int f = threadIdx.x;
    __shared__ u64t ws2[4*C1_*9];
    for (int i = threadIdx.x; i < 4*C1_*9; i += 128) {
        int p = i / (C1_*9), r = i - p*(C1_*9);
        ws2[i] = pk2(g_wf3[(ch*8 + 2*p)*C1_*9 + r],
                     g_wf3[(ch*8 + 2*p + 1)*C1_*9 + r]);
    }
    __syncthreads();

    u64t acc2[4][4];
#pragma unroll
    for (int p = 0; p < 4; p++) {
        u64t bp = pk2(g_bf3[ch*8 + 2*p], g_bf3[ch*8 + 2*p + 1]);
#pragma unroll
        for (int tt = 0; tt < 4; tt++) acc2[p][tt] = bp;
    }

    if (f < FP1_) {
        for (int ci = 0; ci < C1_; ci++) {
            const float* base = g_conv2p + ((b*C1_ + ci)*TP_ + t0)*C2S_ + f;
            float xr[6][3];
#pragma unroll
            for (int j = 0; j < 6; j++)
#pragma unroll
                for (int d = 0; d < 3; d++)
                    xr[j][d] = base[j*C2S_ + d];
#pragma unroll
            for (int k = 0; k < 9; k++) {
                const int dt = k / 3, df = k % 3;
                u64t xk0 = pk2(xr[dt  ][df], xr[dt  ][df]);
                u64t xk1 = pk2(xr[dt+1][df], xr[dt+1][df]);
                u64t xk2 = pk2(xr[dt+2][df], xr[dt+2][df]);
                u64t xk3 = pk2(xr[dt+3][df], xr[dt+3][df]);
#pragma unroll
                for (int p = 0; p < 4; p++) {
                    u64t wv = ws2[(p*C1_ + ci)*9 + k];
                    fma2(acc2[p][0], wv, xk0);
                    fma2(acc2[p][1], wv, xk1);
                    fma2(acc2[p][2], wv, xk2);
                    fma2(acc2[p][3], wv, xk3);
                }
            }
        }
    }
    float acc[8][4];
#pragma unroll
    for (int p = 0; p < 4; p++)
#pragma unroll
        for (int tt = 0; tt < 4; tt++) {
            float2 u = upk2(acc2[p][tt]);
            acc[2*p][tt] = u.x; acc[2*p+1][tt] = u.y;
        }

    const bool wr_ok = ((f & 1) == 0) && ((f >> 1) < FP2_);
#pragma unroll
    for (int cc = 0; cc < 8; cc++) {
        int c = ch*8 + cc;
#pragma unroll
        for (int tt = 0; tt < 4; tt++) {
            float v  = fmaxf(acc[cc][tt], 0.f);
            float vn = __shfl_down_sync(0xffffffffu, v, 1);
            if (wr_ok)
                g_Amat[(b*T_ + t0 + tt)*FCIN_ + c*FP2_ + (f >> 1)] =
                    fmaxf(v, vn);
        }
    }
}

// ---------------- GEMM ----------------
#define BM_ 128
#define BN_ 128
#define BK_ 16
#define ASTR 260
#define BSTR 132
#define GSMEM ((2*BK_*ASTR + 2*BK_*BSTR) * 4)

__global__ __launch_bounds__(256) void gemm_tn(
    const float* __restrict__ A, const float* __restrict__ Bm,
    const float* __restrict__ bias, float* __restrict__ C,
    int M, int N, int K)
{
    extern __shared__ float gsm[];
    float* As = gsm;
    float* Bs = gsm + 2*BK_*ASTR;

    const int tid = threadIdx.x;
    const int m0 = blockIdx.y * BM_, n0 = blockIdx.x * BN_;

    const int lr = tid >> 2;
    const int lk = (tid & 3) * 4;
    const float* Ap = A + (size_t)(m0 + lr) * K + lk;
    const float* Bp = Bm + (size_t)(n0 + lr) * K + lk;
    const size_t rowK = (size_t)64 * K;

    const int warp = tid >> 5, lane = tid & 31;
    const int wm = warp & 3, wn = warp >> 2;
    const int lm = lane >> 3, ln = lane & 7;
    const int row0 = wm * 32 + lm * 8;
    const int col0 = wn * 64 + ln * 8;

    u64t acc2[8][4];
#pragma unroll
    for (int i = 0; i < 8; i++)
#pragma unroll
        for (int j = 0; j < 4; j++) acc2[i][j] = 0ull;

    auto storeA = [&](int buf, const float4& a, int r) {
        float* p = As + (buf*BK_)*ASTR;
        *(float2*)&p[(lk+0)*ASTR + 2*r] = make_float2(a.x, a.x);
        *(float2*)&p[(lk+1)*ASTR + 2*r] = make_float2(a.y, a.y);
        *(float2*)&p[(lk+2)*ASTR + 2*r] = make_float2(a.z, a.z);
        *(float2*)&p[(lk+3)*ASTR + 2*r] = make_float2(a.w, a.w);
    };
    auto storeB = [&](int buf, const float4& b, int r) {
        float* p = Bs + (buf*BK_)*BSTR;
        p[(lk+0)*BSTR + r] = b.x;
        p[(lk+1)*BSTR + r] = b.y;
        p[(lk+2)*BSTR + r] = b.z;
        p[(lk+3)*BSTR + r] = b.w;
    };

    {
        float4 a0 = *(const float4*)(Ap);
        float4 a1 = *(const float4*)(Ap + rowK);
        float4 b0 = *(const float4*)(Bp);
        float4 b1 = *(const float4*)(Bp + rowK);
        storeA(0, a0, lr); storeA(0, a1, lr+64);
        storeB(0, b0, lr); storeB(0, b1, lr+64);
    }
    __syncthreads();

    const int nkt = K >> 4;
    int cur = 0;
    for (int kt = 0; kt < nkt; kt++) {
        float4 pa0, pa1, pb0, pb1;
        const bool has = (kt + 1 < nkt);
        if (has) {
            int ko = (kt + 1) << 4;
            pa0 = *(const float4*)(Ap + ko);
            pa1 = *(const float4*)(Ap + rowK + ko);
            pb0 = *(const float4*)(Bp + ko);
            pb1 = *(const float4*)(Bp + rowK + ko);
        }
#pragma unroll
        for (int kk = 0; kk < BK_; kk++) {
            const float* Ak = As + (cur*BK_ + kk)*ASTR + 2*row0;
            const float* Bk = Bs + (cur*BK_ + kk)*BSTR + col0;
            float4 ad0 = *(const float4*)(Ak);
            float4 ad1 = *(const float4*)(Ak + 4);
            float4 ad2 = *(const float4*)(Ak + 8);
            float4 ad3 = *(const float4*)(Ak + 12);
            float4 bv0 = *(const float4*)(Bk);
            float4 bv1 = *(const float4*)(Bk + 4);
            u64t ai[8] = {lo2(ad0), hi2(ad0), lo2(ad1), hi2(ad1),
                          lo2(ad2), hi2(ad2), lo2(ad3), hi2(ad3)};
            u64t bj[4] = {lo2(bv0), hi2(bv0), lo2(bv1), hi2(bv1)};
#pragma unroll
            for (int i = 0; i < 8; i++)
#pragma unroll
                for (int j = 0; j < 4; j++)
                    fma2(acc2[i][j], ai[i], bj[j]);
        }
        if (has) {
            int nb = cur ^ 1;
            storeA(nb, pa0, lr); storeA(nb, pa1, lr+64);
            storeB(nb, pb0, lr); storeB(nb, pb1, lr+64);
        }
        __syncthreads();
        cur ^= 1;
    }

    float bv[8];
#pragma unroll
    for (int j = 0; j < 8; j++) bv[j] = bias[n0 + col0 + j];
#pragma unroll
    for (int i = 0; i < 8; i++) {
        float* Cp = C + (size_t)(m0 + row0 + i) * N + n0 + col0;
        float2 r0 = upk2(acc2[i][0]), r1 = upk2(acc2[i][1]);
        float2 r2 = upk2(acc2[i][2]), r3 = upk2(acc2[i][3]);
        float4 o0 = make_float4(r0.x+bv[0], r0.y+bv[1], r1.x+bv[2], r1.y+bv[3]);
        float4 o1 = make_float4(r2.x+bv[4], r2.y+bv[5], r3.x+bv[6], r3.y+bv[7]);
        *(float4*)(Cp)     = o0;
        *(float4*)(Cp + 4) = o1;
    }
}

// ---------------- AR persistent kernel ----------------
__device__ __forceinline__ float warp_sum(float s)
{
    s += __shfl_xor_sync(0xffffffffu, s, 16);
    s += __shfl_xor_sync(0xffffffffu, s, 8);
    s += __shfl_xor_sync(0xffffffffu, s, 4);
    s += __shfl_xor_sync(0xffffffffu, s, 2);
    s += __shfl_xor_sync(0xffffffffu, s, 1);
    return s;
}
__device__ __forceinline__ float sigm(float x) { return 1.f / (1.f + expf(-x)); }

// proven barrier: arrival counter + adjacent release word (R14 exact)
__device__ __forceinline__ void gbar(unsigned gen)
{
    __syncthreads();
    if (threadIdx.x == 0) {
        __threadfence();
        unsigned a = atomicAdd(&g_cnt2, 1u) + 1u;
        if (a == gen * NB_AR) {
            g_rel2 = gen;
        } else {
            while (g_rel2 < gen) { }
        }
    }
    __syncthreads();
}

// staged pairwise reduction
__device__ __forceinline__ void reduce32(float* v, int lane)
{
#pragma unroll
    for (int o = 16; o > 0; o >>= 1) {
        bool hi = (lane & o) != 0;
#pragma unroll
        for (int i = 0; i < o; i++) {
            float a0 = v[i], a1 = v[i + o];
            float mine = hi ? a1 : a0;
            float send = hi ? a0 : a1;
            float other = __shfl_xor_sync(0xffffffffu, send, o);
            v[i] = mine + other;
        }
    }
}

template<int NITER>
__device__ __forceinline__ void gemv_part(
    const float* __restrict__ Wb, int wstride,
    const float* xb, int xstride, int lane, float* v)
{
    u64t acc[4][8];
#pragma unroll
    for (int r = 0; r < 4; r++)
#pragma unroll
        for (int b = 0; b < 8; b++) acc[r][b] = 0ull;

#pragma unroll
    for (int it = 0; it < NITER; it++) {
        int off = it * 128 + lane * 4;
        float4 w0 = *(const float4*)(Wb              + off);
        float4 w1 = *(const float4*)(Wb +   wstride  + off);
        float4 w2 = *(const float4*)(Wb + 2*wstride  + off);
        float4 w3 = *(const float4*)(Wb + 3*wstride  + off);
#pragma unroll
        for (int b = 0; b < 8; b++) {
            float4 x = *(const float4*)(xb + b*xstride + off);
            u64t x0 = lo2(x), x1 = hi2(x);
            fma2(acc[0][b], lo2(w0), x0); fma2(acc[0][b], hi2(w0), x1);
            fma2(acc[1][b], lo2(w1), x0); fma2(acc[1][b], hi2(w1), x1);
            fma2(acc[2][b], lo2(w2), x0); fma2(acc[2][b], hi2(w2), x1);
            fma2(acc[3][b], lo2(w3), x0); fma2(acc[3][b], hi2(w3), x1);
        }
    }
#pragma unroll
    for (int r = 0; r < 4; r++)
#pragma unroll
        for (int b = 0; b < 8; b++) v[r*8 + b] = psum(acc[r][b]);
}

// smem float offsets (58096 floats = 232384 B <= 232448 B limit)
#define SW2   0        /* 6*4*1536 = 36864 */
#define SWP   36864    /* 2*5*768  =  7680 */
#define SXS   44544    /* 8*1536   = 12288 */
#define SP2   56832    /* 384 */
#define SPH   57216    /* 384 */
#define SPRE  57600    /* 384 */
#define SC1   57984    /* 48 */
#define SC2   58032    /* 48 */
#define SEMB  58080    /* 16 (10 used) */
#define STOT  58096

__global__ __launch_bounds__(384, 1) void ar_kernel(
    const float* __restrict__ postw, const float* __restrict__ postb,
    const float* __restrict__ embw, float* __restrict__ out)
{
    extern __shared__ float sm[];
    float* w2s  = sm + SW2;
    float* wps  = sm + SWP;
    float* xs2  = sm + SXS;
    float* p2   = sm + SP2;
    float* ph   = sm + SPH;
    float* preS = sm + SPRE;
    float* c1s  = sm + SC1;
    float* c2s  = sm + SC2;
    float* embS = sm + SEMB;

    const int tid = threadIdx.x, lane = tid & 31, warp = tid >> 5;
    const int cl = warp >> 1, half = warp & 1;
    const int cell = blockIdx.x * 6 + cl;

    // ---- one-time loads ----
    {
        const float4* src = (const float4*)(g_W2r + (size_t)blockIdx.x * 6 * 4 * K2_);
        float4* dst = (float4*)w2s;
        for (int i = tid; i < 6*4*K2_/4; i += 384) dst[i] = src[i];
    }
    {
        const float4* s0 = (const float4*)(postw + (size_t)(blockIdx.x >> 1) * 5 * DC_);
        float4* d0 = (float4*)wps;
        for (int i = tid; i < 5*DC_/4; i += 384) d0[i] = s0[i];
        if (blockIdx.x < 48) {
            const float4* s1 = (const float4*)(postw + (size_t)((NB_AR + blockIdx.x) >> 1) * 5 * DC_);
            float4* d1 = (float4*)(wps + 5*DC_);
            for (int i = tid; i < 5*DC_/4; i += 384) d1[i] = s1[i];
        }
    }
    for (int i = tid; i < 12288; i += 384) xs2[i] = 0.f;
    for (int i = tid; i < 384;   i += 384) ph[i] = 0.f;
    if (tid < 48) { c1s[tid] = 0.f; c2s[tid] = 0.f; }
    if (tid < 10) embS[tid] = embw[tid];
    if (tid < 192) {
        int b = tid / 24, j = tid - b*24;
        preS[tid] = __ldg(&g_pre[(size_t)(b*T_)*G4_ + blockIdx.x*24 + j]);
    }
    __syncthreads();

    float v[32];
    unsigned gen = 0;

    for (int t = 0; t < T_; t++) {
        const int wr = (t & 1) ^ 1, pbuf = t & 1;

        // ======== Phase A: emb-part GEMV + combine -> h1_new ========
        for (int i = tid; i < B_*44; i += 384) {
            int b = i / 44, j = i - b*44;
            ((float4*)(xs2 + b*K2_))[j] = __ldcg((const float4*)&g_xemb[b][0] + j);
        }
        __syncthreads();
        gemv_part<1>(g_W1r + (size_t)cell*4*K1P_ + half*128, K1P_,
                     xs2 + half*128, K2_, lane, v);
        reduce32(v, lane);
        p2[warp*32 + lane] = v[0];
        __syncthreads();
        if (tid < 48) {
            int c = tid >> 3, b = tid & 7;
            int mycell = blockIdx.x*6 + c;
            float z[4];
#pragma unroll
            for (int r = 0; r < 4; r++) {
                int idx = r*8 + b;
                z[r] = p2[(c*2)*32 + idx] + p2[(c*2+1)*32 + idx]
                     + ph[(c*2)*32 + idx] + ph[(c*2+1)*32 + idx]
                     + preS[pbuf*192 + b*24 + c*4 + r];
            }
            float co = c1s[tid];
            float ig = sigm(z[0]), fg = sigm(z[1]);
            float gg = tanhf(z[2]), og = sigm(z[3]);
            float cn = fg*co + ig*gg;
            c1s[tid] = cn;
            g_h1[wr][b][mycell] = og * tanhf(cn);
        }
        gbar(++gen);

        // ======== Phase B: LSTM2 ========
        for (int i = tid; i < B_*(DC_/4); i += 384) {
            int b = i / (DC_/4), j = i - b*(DC_/4);
            ((float4*)(xs2 + b*K2_))[j] = __ldcg((const float4*)&g_h1[wr][b][0] + j);
        }
        __syncthreads();
        gemv_part<6>(w2s + cl*4*K2_ + half*DC_, K2_,
                     xs2 + half*DC_, K2_, lane, v);
        reduce32(v, lane);
        p2[warp*32 + lane] = v[0];
        __syncthreads();
        if (tid < 48) {
            int c = tid >> 3, b = tid & 7;
            int mycell = blockIdx.x*6 + c;
            float z[4];
#pragma unroll
            for (int r = 0; r < 4; r++) {
                int idx = r*8 + b;
                z[r] = p2[(c*2)*32 + idx] + p2[(c*2+1)*32 + idx]
                     + __ldg(&g_b2v[mycell*4 + r]);
            }
            float co = c2s[tid];
            float ig = sigm(z[0]), fg = sigm(z[1]);
            float gg = tanhf(z[2]), og = sigm(z[3]);
            float cn = fg*co + ig*gg;
            c2s[tid] = cn;
            g_h2[wr][b][mycell] = og * tanhf(cn);
        }
        gbar(++gen);

        // ======== Phase C: stage h2_new; deferred h1 GEMV; post + argmax ========
        for (int i = tid; i < B_*(DC_/4); i += 384) {
            int b = i / (DC_/4), j = i - b*(DC_/4);
            ((float4*)(xs2 + b*K2_ + DC_))[j] = __ldcg((const float4*)&g_h2[wr][b][0] + j);
        }
        if (t + 1 < T_ && tid < 192) {
            int b = tid / 24, j = tid - b*24;
            preS[(pbuf^1)*192 + tid] = __ldg(&g_pre[(size_t)(b*T_ + t + 1)*G4_ + blockIdx.x*24 + j]);
        }
        __syncthreads();

        gemv_part<3>(g_W1r + (size_t)cell*4*K1P_ + 256 + half*384, K1P_,
                     xs2 + half*384, K2_, lane, v);
        reduce32(v, lane);
        ph[warp*32 + lane] = v[0];

        if (warp < 2 && (warp == 0 || blockIdx.x < 48)) {
            int task = warp * NB_AR + blockIdx.x;
            int p = task >> 1, bh = (task & 1) * 4;
            const float* Wp = wps + warp * 5 * DC_;
            u64t acc[5][4];
#pragma unroll
            for (int s = 0; s < 5; s++)
#pragma unroll
                for (int b = 0; b < 4; b++) acc[s][b] = 0ull;
#pragma unroll 2
            for (int kb = 0; kb < DC_; kb += 128) {
                int off = kb + lane*4;
                float4 w[5];
#pragma unroll
                for (int s = 0; s < 5; s++)
                    w[s] = *(const float4*)(Wp + s*DC_ + off);
#pragma unroll
                for (int b = 0; b < 4; b++) {
                    float4 x = *(const float4*)(xs2 + (bh + b)*K2_ + DC_ + off);
                    u64t x0 = lo2(x), x1 = hi2(x);
#pragma unroll
                    for (int s = 0; s < 5; s++) {
                        fma2(acc[s][b], lo2(w[s]), x0);
                        fma2(acc[s][b], hi2(w[s]), x1);
                    }
                }
            }
            float z[5][4];
#pragma unroll
            for (int s = 0; s < 5; s++)
#pragma unroll
                for (int b = 0; b < 4; b++)
                    z[s][b] = warp_sum(psum(acc[s][b]));
            if (lane < 4) {
                int b = bh + lane;
                float* o = out + (size_t)(b*T_ + t)*440 + p*5;
                float best = -1e30f; int bi = 0;
#pragma unroll
                for (int s = 0; s < 5; s++) {
                    float v0 = (lane & 1) ? z[s][1] : z[s][0];
                    float v1 = (lane & 1) ? z[s][3] : z[s][2];
                    float vv = ((lane & 2) ? v1 : v0) + __ldg(&postb[p*5 + s]);
                    o[s] = vv;
                    if (vv > best) { best = vv; bi = s; }
                }
                g_xemb[b][p*2]     = embS[bi*2];
                g_xemb[b][p*2 + 1] = embS[bi*2 + 1];
            }
        }
        gbar(++gen);
    }
}

// ---------------- launch ----------------
extern "C" void kernel_launch(void* const* d_in, const int* in_sizes, int n_in,
                              void* d_out, int out_size)
{
    const float* mel    = (const float*)d_in[0];
    const float* c1w    = (const float*)d_in[1];
    const float* c1b    = (const float*)d_in[2];
    const float* b1g    = (const float*)d_in[3];
    const float* b1b    = (const float*)d_in[4];
    const float* b1m    = (const float*)d_in[5];
    const float* b1v    = (const float*)d_in[6];
    const float* c2w    = (const float*)d_in[7];
    const float* c2b    = (const float*)d_in[8];
    const float* b2g    = (const float*)d_in[9];
    const float* b2b    = (const float*)d_in[10];
    const float* b2m    = (const float*)d_in[11];
    const float* b2v    = (const float*)d_in[12];
    const float* c3w    = (const float*)d_in[13];
    const float* c3b    = (const float*)d_in[14];
    const float* b3g    = (const float*)d_in[15];
    const float* b3b    = (const float*)d_in[16];
    const float* b3m    = (const float*)d_in[17];
    const float* b3v    = (const float*)d_in[18];
    const float* fc_w   = (const float*)d_in[19];
    const float* fc_b   = (const float*)d_in[20];
    const float* wih1   = (const float*)d_in[21];
    const float* whh1   = (const float*)d_in[22];
    const float* bih1   = (const float*)d_in[23];
    const float* bhh1   = (const float*)d_in[24];
    const float* wih2   = (const float*)d_in[25];
    const float* whh2   = (const float*)d_in[26];
    const float* bih2   = (const float*)d_in[27];
    const float* bhh2   = (const float*)d_in[28];
    const float* post_w = (const float*)d_in[29];
    const float* post_b = (const float*)d_in[30];
    const float* emb_w  = (const float*)d_in[31];

    prep_kernel<<<2048, 256>>>(c1w, c1b, b1g, b1b, b1m, b1v,
                               c2w, c2b, b2g, b2b, b2m, b2v,
                               c3w, c3b, b3g, b3b, b3m, b3v,
                               wih1, whh1, bih1, bhh1,
                               wih2, whh2, bih2, bhh2, emb_w);

    conv1_kernel<<<dim3(T_, B_), 256>>>(mel);
    conv2_kernel<<<dim3(T_/4, B_, C1_/8), 256>>>();
    conv3_kernel<<<dim3(T_/4, B_, C3_/8), 128>>>();

    float *pA, *pAc, *pPre, *pWpre, *pBpre;
    cudaGetSymbolAddress((void**)&pA,    g_Amat);
    cudaGetSymbolAddress((void**)&pAc,   g_ac);
    cudaGetSymbolAddress((void**)&pPre,  g_pre);
    cudaGetSymbolAddress((void**)&pWpre, g_Wpre);
    cudaGetSymbolAddress((void**)&pBpre, g_bpre);

    cudaFuncSetAttribute(gemm_tn, cudaFuncAttributeMaxDynamicSharedMemorySize, GSMEM);
    gemm_tn<<<dim3(DC_/BN_, MALL_/BM_), 256, GSMEM>>>(pA, fc_w, fc_b, pAc, MALL_, DC_, FCIN_);
    gemm_tn<<<dim3(G4_/BN_, MALL_/BM_), 256, GSMEM>>>(pAc, pWpre, pBpre, pPre, MALL_, G4_, DC_);

    const int ar_smem = STOT * (int)sizeof(float);  // 232384 B
    cudaFuncSetAttribute(ar_kernel, cudaFuncAttributeMaxDynamicSharedMemorySize, ar_smem);
    ar_kernel<<<NB_AR, 384, ar_smem>>>(post_w, post_b, emb_w, (float*)d_out);
}